// round 1
// baseline (speedup 1.0000x reference)
#include <cuda_runtime.h>
#include <math.h>

// ============================================================
// Static device scratch (no allocations allowed)
// ============================================================
__device__ float g_x[512 * 1024];        // attention state, C-major (c*1024 + tok)
__device__ float g_t[1024 * 512];        // tokens (N, C)
__device__ float g_qkv[1024 * 1536];     // qkv projection
__device__ float g_attn[8 * 1024 * 1024];// per-head attention logits/probs
__device__ float g_res[1024 * 512];      // attention output tokens
__device__ float g_xs[512 * 2500];       // grid-sampled 50x50
__device__ float g_h[512 * 2500];        // EDSR head output
__device__ float g_r[512 * 2500];        // EDSR running residual
__device__ float g_tmp[512 * 2500];      // EDSR temp
__device__ float g_u[512 * 10000];       // pixel-shuffled 100x100
__device__ float g_y1[512 * 10000];
__device__ float g_y2[512 * 10000];
__device__ float g_bn[2048];             // bn1 scale/shift, bn2 scale/shift

// ============================================================
// Transpose g_x (512 x 1024) -> g_t (1024 x 512)
// ============================================================
__global__ void k_transpose() {
    __shared__ float s[32][33];
    int bx = blockIdx.x, by = blockIdx.y;
    int tx = threadIdx.x, ty = threadIdx.y;
#pragma unroll
    for (int i = 0; i < 32; i += 8)
        s[ty + i][tx] = g_x[(by * 32 + ty + i) * 1024 + bx * 32 + tx];
    __syncthreads();
#pragma unroll
    for (int i = 0; i < 32; i += 8)
        g_t[(bx * 32 + ty + i) * 512 + by * 32 + tx] = s[tx][ty + i];
}

// ============================================================
// Generic SGEMM: C[MxN] = A[MxK] @ B[KxN] (+bias per col).
// If addT != null: addT[n*M + m] += val   (transposed residual add)
// Requires M,N,K multiples of 64/64/16.
// ============================================================
__global__ __launch_bounds__(256)
void k_sgemm(const float* __restrict__ A, const float* __restrict__ B,
             float* __restrict__ Cout, int M, int N, int K,
             const float* __restrict__ bias, float* __restrict__ addT) {
    __shared__ float As[16][68];
    __shared__ float Bs[16][64];
    int m0 = blockIdx.y * 64, n0 = blockIdx.x * 64;
    int tid = threadIdx.x;
    int tx = tid & 15, ty = tid >> 4;
    float acc[4][4] = {};
    for (int kk = 0; kk < K; kk += 16) {
        {
            int m = tid >> 2, k4 = (tid & 3) * 4;
            float4 a = *(const float4*)(A + (size_t)(m0 + m) * K + kk + k4);
            As[k4 + 0][m] = a.x; As[k4 + 1][m] = a.y;
            As[k4 + 2][m] = a.z; As[k4 + 3][m] = a.w;
        }
        {
            int k = tid >> 4, n4 = (tid & 15) * 4;
            *(float4*)&Bs[k][n4] = *(const float4*)(B + (size_t)(kk + k) * N + n0 + n4);
        }
        __syncthreads();
#pragma unroll
        for (int k = 0; k < 16; k++) {
            float a[4];
#pragma unroll
            for (int i = 0; i < 4; i++) a[i] = As[k][ty * 4 + i];
            float4 b4 = *(const float4*)&Bs[k][tx * 4];
            float b[4] = {b4.x, b4.y, b4.z, b4.w};
#pragma unroll
            for (int i = 0; i < 4; i++)
#pragma unroll
                for (int j = 0; j < 4; j++) acc[i][j] += a[i] * b[j];
        }
        __syncthreads();
    }
#pragma unroll
    for (int i = 0; i < 4; i++) {
        int m = m0 + ty * 4 + i;
#pragma unroll
        for (int j = 0; j < 4; j++) {
            int n = n0 + tx * 4 + j;
            float v = acc[i][j];
            if (bias) v += bias[n];
            if (addT) addT[(size_t)n * M + m] += v;
            else Cout[(size_t)m * N + n] = v;
        }
    }
}

// ============================================================
// Attention scores: per head S = Q @ K^T  (1024x1024, d=64)
// ============================================================
__global__ __launch_bounds__(256)
void k_attn_scores() {
    __shared__ float Qs[16][68];
    __shared__ float Ks[16][68];
    int h = blockIdx.z;
    int m0 = blockIdx.y * 64, n0 = blockIdx.x * 64;
    int tid = threadIdx.x;
    int tx = tid & 15, ty = tid >> 4;
    int qoff = h * 64, koff = 512 + h * 64;
    float acc[4][4] = {};
    for (int kk = 0; kk < 64; kk += 16) {
        int r = tid >> 2, k4 = (tid & 3) * 4;
        float4 q = *(const float4*)(g_qkv + (size_t)(m0 + r) * 1536 + qoff + kk + k4);
        Qs[k4 + 0][r] = q.x; Qs[k4 + 1][r] = q.y; Qs[k4 + 2][r] = q.z; Qs[k4 + 3][r] = q.w;
        float4 kv = *(const float4*)(g_qkv + (size_t)(n0 + r) * 1536 + koff + kk + k4);
        Ks[k4 + 0][r] = kv.x; Ks[k4 + 1][r] = kv.y; Ks[k4 + 2][r] = kv.z; Ks[k4 + 3][r] = kv.w;
        __syncthreads();
#pragma unroll
        for (int k = 0; k < 16; k++) {
            float a[4], b[4];
#pragma unroll
            for (int i = 0; i < 4; i++) a[i] = Qs[k][ty * 4 + i];
#pragma unroll
            for (int j = 0; j < 4; j++) b[j] = Ks[k][tx * 4 + j];
#pragma unroll
            for (int i = 0; i < 4; i++)
#pragma unroll
                for (int j = 0; j < 4; j++) acc[i][j] += a[i] * b[j];
        }
        __syncthreads();
    }
    float* S = g_attn + ((size_t)h << 20);
#pragma unroll
    for (int i = 0; i < 4; i++)
#pragma unroll
        for (int j = 0; j < 4; j++)
            S[(size_t)(m0 + ty * 4 + i) * 1024 + n0 + tx * 4 + j] = acc[i][j];
}

// ============================================================
// Row softmax of scaled logits (8192 rows x 1024)
// ============================================================
__global__ __launch_bounds__(256)
void k_softmax(float scale) {
    float* p = g_attn + (size_t)blockIdx.x * 1024;
    int tid = threadIdx.x;
    float4 v = *(float4*)(p + tid * 4);
    v.x *= scale; v.y *= scale; v.z *= scale; v.w *= scale;
    float mx = fmaxf(fmaxf(v.x, v.y), fmaxf(v.z, v.w));
#pragma unroll
    for (int o = 16; o > 0; o >>= 1) mx = fmaxf(mx, __shfl_xor_sync(0xffffffffu, mx, o));
    __shared__ float sm[8], ss[8];
    if ((tid & 31) == 0) sm[tid >> 5] = mx;
    __syncthreads();
    mx = sm[0];
#pragma unroll
    for (int i = 1; i < 8; i++) mx = fmaxf(mx, sm[i]);
    float e0 = expf(v.x - mx), e1 = expf(v.y - mx), e2 = expf(v.z - mx), e3 = expf(v.w - mx);
    float s = e0 + e1 + e2 + e3;
#pragma unroll
    for (int o = 16; o > 0; o >>= 1) s += __shfl_xor_sync(0xffffffffu, s, o);
    if ((tid & 31) == 0) ss[tid >> 5] = s;
    __syncthreads();
    s = ss[0] + ss[1] + ss[2] + ss[3] + ss[4] + ss[5] + ss[6] + ss[7];
    float inv = 1.f / s;
    float4 o4 = make_float4(e0 * inv, e1 * inv, e2 * inv, e3 * inv);
    *(float4*)(p + tid * 4) = o4;
}

// ============================================================
// O = softmax(S) @ V  -> g_res tokens (N, C)
// ============================================================
__global__ __launch_bounds__(256)
void k_attn_out() {
    __shared__ float As[16][68];
    __shared__ float Bs[16][64];
    int m0 = blockIdx.x * 64, h = blockIdx.y;
    const float* S = g_attn + ((size_t)h << 20);
    int tid = threadIdx.x, tx = tid & 15, ty = tid >> 4;
    float acc[4][4] = {};
    for (int kk = 0; kk < 1024; kk += 16) {
        {
            int m = tid >> 2, k4 = (tid & 3) * 4;
            float4 a = *(const float4*)(S + (size_t)(m0 + m) * 1024 + kk + k4);
            As[k4 + 0][m] = a.x; As[k4 + 1][m] = a.y;
            As[k4 + 2][m] = a.z; As[k4 + 3][m] = a.w;
        }
        {
            int k = tid >> 4, n4 = (tid & 15) * 4;
            *(float4*)&Bs[k][n4] =
                *(const float4*)(g_qkv + (size_t)(kk + k) * 1536 + 1024 + h * 64 + n4);
        }
        __syncthreads();
#pragma unroll
        for (int k = 0; k < 16; k++) {
            float a[4];
#pragma unroll
            for (int i = 0; i < 4; i++) a[i] = As[k][ty * 4 + i];
            float4 b4 = *(const float4*)&Bs[k][tx * 4];
            float b[4] = {b4.x, b4.y, b4.z, b4.w};
#pragma unroll
            for (int i = 0; i < 4; i++)
#pragma unroll
                for (int j = 0; j < 4; j++) acc[i][j] += a[i] * b[j];
        }
        __syncthreads();
    }
#pragma unroll
    for (int i = 0; i < 4; i++)
#pragma unroll
        for (int j = 0; j < 4; j++)
            g_res[(size_t)(m0 + ty * 4 + i) * 512 + h * 64 + tx * 4 + j] = acc[i][j];
}

// ============================================================
// BEVGridTransform: nearest grid sample 32x32 -> 50x50
// (replicates jnp ops in fp32 incl. banker's rounding)
// ============================================================
__device__ __forceinline__ int map_idx(int o, int size, bool* valid) {
    float vv = -49.f + 2.f * (float)o;
    float g = (vv + 51.2f) / 102.4f * 2.f - 1.f;
    float f = ((g + 1.f) * (float)size - 1.f) * 0.5f;
    int ii = (int)rintf(f);
    *valid = (ii >= 0) && (ii < size);
    return min(max(ii, 0), size - 1);
}

__global__ void k_gridsample() {
    int idx = blockIdx.x * 256 + threadIdx.x;
    if (idx >= 512 * 2500) return;
    int c = idx / 2500, p = idx - c * 2500;
    int oy = p / 50, ox = p - oy * 50;
    bool vy, vx;
    int iy = map_idx(oy, 32, &vy);
    int ix = map_idx(ox, 32, &vx);
    g_xs[idx] = (vy && vx) ? g_x[(size_t)c * 1024 + iy * 32 + ix] : 0.f;
}

// ============================================================
// BN fold: scale = g/sqrt(v+eps), shift = b - m*scale
// ============================================================
__global__ void k_bnprep(const float* g1, const float* b1, const float* m1, const float* v1,
                         const float* g2, const float* b2, const float* m2, const float* v2) {
    int c = blockIdx.x * 256 + threadIdx.x;
    if (c >= 512) return;
    float s1 = g1[c] / sqrtf(v1[c] + 1e-5f);
    g_bn[c] = s1;
    g_bn[512 + c] = b1[c] - m1[c] * s1;
    float s2 = g2[c] / sqrtf(v2[c] + 1e-5f);
    g_bn[1024 + c] = s2;
    g_bn[1536 + c] = b2[c] - m2[c] * s2;
}

// ============================================================
// Implicit-GEMM conv3x3 (pad=1), flexible epilogue:
// bias add / BN scale+shift / residual add / relu / pixel-shuffle(r=2)
// Tile: 64 out-channels x 64 pixels, K = CI*9, BK=16
// ============================================================
__global__ __launch_bounds__(256)
void k_conv3x3(const float* __restrict__ in, const float* __restrict__ w,
               const float* __restrict__ bias, const float* __restrict__ bnsc,
               const float* __restrict__ bnsh, const float* __restrict__ resid,
               float* __restrict__ out, int CI, int H, int W, int relu, int ps) {
    __shared__ float As[16][68];
    __shared__ float Bs[16][64];
    const int P = H * W;
    const int K = CI * 9;
    int m0 = blockIdx.y * 64, n0 = blockIdx.x * 64;
    int tid = threadIdx.x, tx = tid & 15, ty = tid >> 4;

    // Precompute pixel coords for this thread's B-load columns
    int lk = tid >> 4;
    int ln4 = (tid & 15) * 4;
    int py[4], px[4];
    bool pv[4];
#pragma unroll
    for (int j = 0; j < 4; j++) {
        int p = n0 + ln4 + j;
        pv[j] = p < P;
        int pp = pv[j] ? p : 0;
        py[j] = pp / W;
        px[j] = pp - py[j] * W;
    }

    float acc[4][4] = {};
    for (int kk = 0; kk < K; kk += 16) {
        {
            int m = tid >> 2, k4 = (tid & 3) * 4;
            float4 a = *(const float4*)(w + (size_t)(m0 + m) * K + kk + k4);
            As[k4 + 0][m] = a.x; As[k4 + 1][m] = a.y;
            As[k4 + 2][m] = a.z; As[k4 + 3][m] = a.w;
        }
        {
            int kg = kk + lk;
            int ci = kg / 9;
            int r9 = kg - ci * 9;
            int ky = r9 / 3;
            int dy = ky - 1, dx = (r9 - ky * 3) - 1;
            const float* ip = in + (size_t)ci * P;
#pragma unroll
            for (int j = 0; j < 4; j++) {
                int yy = py[j] + dy, xx = px[j] + dx;
                float v = 0.f;
                if (pv[j] && yy >= 0 && yy < H && xx >= 0 && xx < W) v = ip[yy * W + xx];
                Bs[lk][ln4 + j] = v;
            }
        }
        __syncthreads();
#pragma unroll
        for (int k = 0; k < 16; k++) {
            float a[4];
#pragma unroll
            for (int i = 0; i < 4; i++) a[i] = As[k][ty * 4 + i];
            float4 b4 = *(const float4*)&Bs[k][tx * 4];
            float b[4] = {b4.x, b4.y, b4.z, b4.w};
#pragma unroll
            for (int i = 0; i < 4; i++)
#pragma unroll
                for (int j = 0; j < 4; j++) acc[i][j] += a[i] * b[j];
        }
        __syncthreads();
    }

#pragma unroll
    for (int i = 0; i < 4; i++) {
        int co = m0 + ty * 4 + i;
        float bv = bias ? bias[co] : 0.f;
        float sc = bnsc ? bnsc[co] : 1.f;
        float sh = bnsh ? bnsh[co] : 0.f;
#pragma unroll
        for (int j = 0; j < 4; j++) {
            int p = n0 + tx * 4 + j;
            if (p >= P) continue;
            float v = acc[i][j] + bv;
            if (bnsc) v = v * sc + sh;
            if (resid) v += resid[(size_t)co * P + p];
            if (relu) v = fmaxf(v, 0.f);
            if (ps) {
                int c = co >> 2, ry = (co >> 1) & 1, rx = co & 1;
                int y = p / W, x = p - (p / W) * W;
                out[(size_t)c * (4 * P) + (size_t)(2 * y + ry) * (2 * W) + 2 * x + rx] = v;
            } else {
                out[(size_t)co * P + p] = v;
            }
        }
    }
}

// ============================================================
// c3: 1x1 conv 512->6 + bias + sigmoid, writes d_out
// ============================================================
__global__ void k_c3(const float* __restrict__ w, const float* __restrict__ b,
                     float* __restrict__ out) {
    int idx = blockIdx.x * 256 + threadIdx.x;
    if (idx >= 60000) return;
    int cls = idx / 10000, p = idx - cls * 10000;
    const float* wr = w + cls * 512;
    float s = b[cls];
#pragma unroll 4
    for (int c = 0; c < 512; c++) s += g_y1[(size_t)c * 10000 + p] * wr[c];
    out[idx] = 1.f / (1.f + expf(-s));
}

// ============================================================
// Host orchestration
// ============================================================
extern "C" void kernel_launch(void* const* d_in, const int* in_sizes, int n_in,
                              void* d_out, int out_size) {
    const float* x       = (const float*)d_in[0];
    const float* qkv_w   = (const float*)d_in[1];
    const float* proj_w  = (const float*)d_in[2];
    const float* proj_b  = (const float*)d_in[3];
    const float* head_w  = (const float*)d_in[4];
    const float* head_b  = (const float*)d_in[5];
    const float* body_w  = (const float*)d_in[6];
    const float* body_b  = (const float*)d_in[7];
    const float* btail_w = (const float*)d_in[8];
    const float* btail_b = (const float*)d_in[9];
    const float* up_w    = (const float*)d_in[10];
    const float* up_b    = (const float*)d_in[11];
    const float* tail_w  = (const float*)d_in[12];
    const float* tail_b  = (const float*)d_in[13];
    const float* c1_w    = (const float*)d_in[14];
    const float* bn1_g   = (const float*)d_in[15];
    const float* bn1_b   = (const float*)d_in[16];
    const float* bn1_m   = (const float*)d_in[17];
    const float* bn1_v   = (const float*)d_in[18];
    const float* c2_w    = (const float*)d_in[19];
    const float* bn2_g   = (const float*)d_in[20];
    const float* bn2_b   = (const float*)d_in[21];
    const float* bn2_m   = (const float*)d_in[22];
    const float* bn2_v   = (const float*)d_in[23];
    const float* c3_w    = (const float*)d_in[24];
    const float* c3_b    = (const float*)d_in[25];
    float* out = (float*)d_out;

    float *p_x, *p_t, *p_qkv, *p_res, *p_xs, *p_h, *p_r, *p_tmp, *p_u, *p_y1, *p_y2, *p_bn;
    cudaGetSymbolAddress((void**)&p_x, g_x);
    cudaGetSymbolAddress((void**)&p_t, g_t);
    cudaGetSymbolAddress((void**)&p_qkv, g_qkv);
    cudaGetSymbolAddress((void**)&p_res, g_res);
    cudaGetSymbolAddress((void**)&p_xs, g_xs);
    cudaGetSymbolAddress((void**)&p_h, g_h);
    cudaGetSymbolAddress((void**)&p_r, g_r);
    cudaGetSymbolAddress((void**)&p_tmp, g_tmp);
    cudaGetSymbolAddress((void**)&p_u, g_u);
    cudaGetSymbolAddress((void**)&p_y1, g_y1);
    cudaGetSymbolAddress((void**)&p_y2, g_y2);
    cudaGetSymbolAddress((void**)&p_bn, g_bn);

    cudaMemcpyAsync(p_x, x, (size_t)512 * 1024 * sizeof(float),
                    cudaMemcpyDeviceToDevice, 0);

    const float scale = 0.044194173824159216f;  // 512^-0.5

    // ---- 8 self-attention blocks ----
    for (int i = 0; i < 8; i++) {
        k_transpose<<<dim3(32, 16), dim3(32, 8)>>>();
        k_sgemm<<<dim3(24, 16), 256>>>(p_t, qkv_w + (size_t)i * 512 * 1536, p_qkv,
                                       1024, 1536, 512, nullptr, nullptr);
        k_attn_scores<<<dim3(16, 16, 8), 256>>>();
        k_softmax<<<8192, 256>>>(scale);
        k_attn_out<<<dim3(16, 8), 256>>>();
        k_sgemm<<<dim3(8, 16), 256>>>(p_res, proj_w + (size_t)i * 512 * 512, nullptr,
                                      1024, 512, 512, proj_b + (size_t)i * 512, p_x);
    }

    // ---- grid transform + BN fold ----
    k_gridsample<<<(512 * 2500 + 255) / 256, 256>>>();
    k_bnprep<<<2, 256>>>(bn1_g, bn1_b, bn1_m, bn1_v, bn2_g, bn2_b, bn2_m, bn2_v);

    // ---- EDSR upsampler ----
    dim3 g50((2500 + 63) / 64, 8);
    k_conv3x3<<<g50, 256>>>(p_xs, head_w, head_b, nullptr, nullptr, nullptr,
                            p_h, 512, 50, 50, 0, 0);
    cudaMemcpyAsync(p_r, p_h, (size_t)512 * 2500 * sizeof(float),
                    cudaMemcpyDeviceToDevice, 0);
    for (int i = 0; i < 8; i++) {
        k_conv3x3<<<g50, 256>>>(p_r, body_w + (size_t)(2 * i) * 512 * 512 * 9,
                                body_b + (size_t)(2 * i) * 512,
                                nullptr, nullptr, nullptr, p_tmp, 512, 50, 50, 1, 0);
        k_conv3x3<<<g50, 256>>>(p_tmp, body_w + (size_t)(2 * i + 1) * 512 * 512 * 9,
                                body_b + (size_t)(2 * i + 1) * 512,
                                nullptr, nullptr, p_r, p_r, 512, 50, 50, 0, 0);
    }
    k_conv3x3<<<g50, 256>>>(p_r, btail_w, btail_b, nullptr, nullptr, p_h,
                            p_tmp, 512, 50, 50, 0, 0);
    // up conv (512->2048) with fused pixel shuffle -> g_u (512 x 100 x 100)
    k_conv3x3<<<dim3((2500 + 63) / 64, 32), 256>>>(p_tmp, up_w, up_b, nullptr, nullptr,
                                                   nullptr, p_u, 512, 50, 50, 0, 1);
    dim3 g100((10000 + 63) / 64, 8);
    k_conv3x3<<<g100, 256>>>(p_u, tail_w, tail_b, nullptr, nullptr, nullptr,
                             p_y1, 512, 100, 100, 0, 0);

    // ---- classifier ----
    k_conv3x3<<<g100, 256>>>(p_y1, c1_w, nullptr, p_bn, p_bn + 512, nullptr,
                             p_y2, 512, 100, 100, 1, 0);
    k_conv3x3<<<g100, 256>>>(p_y2, c2_w, nullptr, p_bn + 1024, p_bn + 1536, nullptr,
                             p_y1, 512, 100, 100, 1, 0);
    k_c3<<<(60000 + 255) / 256, 256>>>(c3_w, c3_b, out);
}

// round 3
// speedup vs baseline: 1.9309x; 1.9309x over previous
#include <cuda_runtime.h>
#include <cuda_bf16.h>
#include <math.h>
#include <stdint.h>

// ============================================================
// Static device scratch (no allocations allowed)
// ============================================================
__device__ float g_x[512 * 1024];        // attention state, C-major (c*1024 + tok)
__device__ float g_t[1024 * 512];        // tokens (N, C)
__device__ float g_qkv[1024 * 1536];     // qkv projection
__device__ float g_attn[8 * 1024 * 1024];// per-head attention logits/probs
__device__ float g_res[1024 * 512];      // attention output tokens
__device__ float g_xs[512 * 2500];       // grid-sampled 50x50
__device__ float g_h[512 * 2500];        // EDSR head output
__device__ float g_r[512 * 2500];        // EDSR running residual
__device__ float g_tmp[512 * 2500];      // EDSR temp
__device__ float g_u[512 * 10000];       // pixel-shuffled 100x100
__device__ float g_y1[512 * 10000];
__device__ float g_y2[512 * 10000];
__device__ float g_bn[2048];             // bn1 scale/shift, bn2 scale/shift

// bf16 split weights for all convs (hi + lo)
#define W_HEAD  0
#define W_BODY  2359296
#define W_BTAIL 40108032
#define W_UP    42467328
#define W_TAIL  51904512
#define W_C1    54263808
#define W_C2    56623104
#define W_TOTAL 58982400
__device__ __nv_bfloat16 g_whi[W_TOTAL];
__device__ __nv_bfloat16 g_wlo[W_TOTAL];

// ============================================================
// Helpers
// ============================================================
__device__ __forceinline__ uint32_t smem_u32(const void* p) {
    uint32_t a;
    asm("{ .reg .u64 t; cvta.to.shared.u64 t, %1; cvt.u32.u64 %0, t; }"
        : "=r"(a) : "l"(p));
    return a;
}

__device__ __forceinline__ void ldsm4(uint32_t addr, uint32_t* r) {
    asm volatile("ldmatrix.sync.aligned.m8n8.x4.shared.b16 {%0,%1,%2,%3}, [%4];"
                 : "=r"(r[0]), "=r"(r[1]), "=r"(r[2]), "=r"(r[3]) : "r"(addr));
}

__device__ __forceinline__ void mma16816(float* d, const uint32_t* a,
                                         uint32_t b0, uint32_t b1) {
    asm volatile(
        "mma.sync.aligned.m16n8k16.row.col.f32.bf16.bf16.f32 "
        "{%0,%1,%2,%3}, {%4,%5,%6,%7}, {%8,%9}, {%0,%1,%2,%3};"
        : "+f"(d[0]), "+f"(d[1]), "+f"(d[2]), "+f"(d[3])
        : "r"(a[0]), "r"(a[1]), "r"(a[2]), "r"(a[3]), "r"(b0), "r"(b1));
}

// ============================================================
// Weight split: fp32 -> (bf16 hi, bf16 lo)
// ============================================================
__global__ void k_wprep(const float* __restrict__ src, __nv_bfloat16* __restrict__ hi,
                        __nv_bfloat16* __restrict__ lo, int n) {
    int i = blockIdx.x * 256 + threadIdx.x;
    if (i >= n) return;
    float v = src[i];
    __nv_bfloat16 h = __float2bfloat16(v);
    hi[i] = h;
    lo[i] = __float2bfloat16(v - __bfloat162float(h));
}

// ============================================================
// mma.sync implicit-GEMM conv3x3 (pad=1), 3-term bf16 split.
// Tile: M=128 out-ch x N=64 pixels, K=4608 (CI=512*9), chunks of 32.
// 8 warps: warp_m = wid&3 (32 rows), warp_n = wid>>2 (32 pixels).
// Double-buffered smem, row pitch 80B ([row][32 k] bf16 + 8 pad).
// Epilogue: bias / BN / residual / relu / pixel-shuffle(2).
// ============================================================
#define PITCH 80                 // bytes per smem row (40 halves)
#define OFF_AHI 0                // 128 rows
#define OFF_ALO (128 * PITCH)    // 10240
#define OFF_BHI (2 * 128 * PITCH)
#define OFF_BLO (2 * 128 * PITCH + 64 * PITCH)
#define STAGE   (2 * 128 * PITCH + 2 * 64 * PITCH)   // 30720
#define SMEM_DYN (2 * STAGE)                          // 61440

__global__ __launch_bounds__(256, 2)
void k_convtc(const float* __restrict__ in,
              const __nv_bfloat16* __restrict__ whi,
              const __nv_bfloat16* __restrict__ wlo,
              const float* __restrict__ bias,
              const float* __restrict__ bnsc, const float* __restrict__ bnsh,
              const float* __restrict__ resid, float* __restrict__ out,
              int H, int W, int relu, int ps) {
    extern __shared__ char sm[];
    const int P = H * W;
    const int K = 4608;
    int tid = threadIdx.x, wid = tid >> 5, lane = tid & 31;
    int n0 = blockIdx.x * 64, m0 = blockIdx.y * 128;
    uint32_t sb = smem_u32(sm);

    // ---------------- loader assignments ----------------
    // A: 2 threads per row; each loads 32B (16 halves) hi + lo
    int arow = tid >> 1, aseg = tid & 1;
    const __nv_bfloat16* whp = whi + (size_t)(m0 + arow) * K + aseg * 16;
    const __nv_bfloat16* wlp = wlo + (size_t)(m0 + arow) * K + aseg * 16;
    uint32_t a_st = sb + arow * PITCH + aseg * 32;

    // B: pixel = tid&63, kgroup = tid>>6 (8 k each)
    int bpix = tid & 63, bkg = tid >> 6;
    int pg = n0 + bpix;
    bool pval = pg < P;
    int pc = pval ? pg : 0;
    int py = pc / W, px = pc - py * W;
    uint32_t b_st = sb + OFF_BHI + bpix * PITCH + bkg * 16;

    // staging registers
    uint4 rAh[2], rAl[2];
    float rB[8];

    auto load_gmem = [&](int ch) {
        int kk = ch << 5;
        rAh[0] = *(const uint4*)(whp + kk);
        rAh[1] = *(const uint4*)(whp + kk + 8);
        rAl[0] = *(const uint4*)(wlp + kk);
        rAl[1] = *(const uint4*)(wlp + kk + 8);
#pragma unroll
        for (int j = 0; j < 8; j++) {
            int k = kk + bkg * 8 + j;
            int ci = k / 9;
            int r9 = k - ci * 9;
            int ky = r9 / 3;
            int dy = ky - 1, dx = (r9 - ky * 3) - 1;
            int yy = py + dy, xx = px + dx;
            float v = 0.f;
            if (pval && (unsigned)yy < (unsigned)H && (unsigned)xx < (unsigned)W)
                v = in[(size_t)ci * P + yy * W + xx];
            rB[j] = v;
        }
    };

    auto store_smem = [&](int buf) {
        uint32_t bo = buf * STAGE;
        *(uint4*)(sm + (a_st - sb) + bo) = rAh[0];
        *(uint4*)(sm + (a_st - sb) + bo + 16) = rAh[1];
        *(uint4*)(sm + (a_st - sb) + bo + OFF_ALO) = rAl[0];
        *(uint4*)(sm + (a_st - sb) + bo + OFF_ALO + 16) = rAl[1];
#pragma unroll
        for (int j = 0; j < 8; j += 2) {
            float v0 = rB[j], v1 = rB[j + 1];
            __nv_bfloat16 h0 = __float2bfloat16(v0);
            __nv_bfloat16 h1 = __float2bfloat16(v1);
            __nv_bfloat16 l0 = __float2bfloat16(v0 - __bfloat162float(h0));
            __nv_bfloat16 l1 = __float2bfloat16(v1 - __bfloat162float(h1));
            uint32_t hp = (uint32_t)__bfloat16_as_ushort(h0) |
                          ((uint32_t)__bfloat16_as_ushort(h1) << 16);
            uint32_t lp = (uint32_t)__bfloat16_as_ushort(l0) |
                          ((uint32_t)__bfloat16_as_ushort(l1) << 16);
            *(uint32_t*)(sm + (b_st - sb) + bo + j * 2) = hp;
            *(uint32_t*)(sm + (b_st - sb) + bo + (OFF_BLO - OFF_BHI) + j * 2) = lp;
        }
    };

    // ---------------- mma assignments ----------------
    int warp_m = wid & 3, warp_n = wid >> 2;
    // ldmatrix lane offset: row = lane&15, k-half = lane>>4
    uint32_t a_ld = sb + (warp_m * 32 + (lane & 15)) * PITCH + (lane >> 4) * 16;
    uint32_t b_ld = sb + OFF_BHI + (warp_n * 32 + (lane & 15)) * PITCH + (lane >> 4) * 16;

    float acc[2][4][4];
#pragma unroll
    for (int i = 0; i < 2; i++)
#pragma unroll
        for (int j = 0; j < 4; j++)
#pragma unroll
            for (int e = 0; e < 4; e++) acc[i][j][e] = 0.f;

    load_gmem(0);
    store_smem(0);
    __syncthreads();

    for (int ch = 0; ch < 144; ch++) {
        if (ch < 143) load_gmem(ch + 1);
        uint32_t bo = (ch & 1) * STAGE;
#pragma unroll
        for (int ks = 0; ks < 2; ks++) {
            uint32_t Ah[2][4], Al[2][4], Bh[2][4], Bl[2][4];
#pragma unroll
            for (int mt = 0; mt < 2; mt++) {
                ldsm4(a_ld + bo + mt * (16 * PITCH) + ks * 32, Ah[mt]);
                ldsm4(a_ld + bo + OFF_ALO + mt * (16 * PITCH) + ks * 32, Al[mt]);
            }
#pragma unroll
            for (int g = 0; g < 2; g++) {
                ldsm4(b_ld + bo + g * (16 * PITCH) + ks * 32, Bh[g]);
                ldsm4(b_ld + bo + (OFF_BLO - OFF_BHI) + g * (16 * PITCH) + ks * 32, Bl[g]);
            }
#pragma unroll
            for (int mt = 0; mt < 2; mt++)
#pragma unroll
                for (int nt = 0; nt < 4; nt++) {
                    int g = nt >> 1, idx = nt & 1;
                    uint32_t bh0 = Bh[g][idx], bh1 = Bh[g][idx + 2];
                    uint32_t bl0 = Bl[g][idx], bl1 = Bl[g][idx + 2];
                    mma16816(acc[mt][nt], Ah[mt], bh0, bh1);
                    mma16816(acc[mt][nt], Ah[mt], bl0, bl1);
                    mma16816(acc[mt][nt], Al[mt], bh0, bh1);
                }
        }
        if (ch < 143) {
            store_smem((ch + 1) & 1);
            __syncthreads();
        }
    }

    // ---------------- epilogue ----------------
#pragma unroll
    for (int mt = 0; mt < 2; mt++) {
#pragma unroll
        for (int half = 0; half < 2; half++) {
            int co = m0 + warp_m * 32 + mt * 16 + (lane >> 2) + half * 8;
            float bv = bias ? bias[co] : 0.f;
            float sc = bnsc ? bnsc[co] : 1.f;
            float sh = bnsh ? bnsh[co] : 0.f;
#pragma unroll
            for (int nt = 0; nt < 4; nt++) {
#pragma unroll
                for (int e = 0; e < 2; e++) {
                    int p = n0 + warp_n * 32 + nt * 8 + (lane & 3) * 2 + e;
                    if (p >= P) continue;
                    float v = acc[mt][nt][half * 2 + e];
                    v += bv;
                    if (bnsc) v = v * sc + sh;
                    if (resid) v += resid[(size_t)co * P + p];
                    if (relu) v = fmaxf(v, 0.f);
                    if (ps) {
                        int c = co >> 2, ry = (co >> 1) & 1, rx = co & 1;
                        int yy = p / W, xx = p - (p / W) * W;
                        out[(size_t)c * (4 * P) + (size_t)(2 * yy + ry) * (2 * W) +
                            2 * xx + rx] = v;
                    } else {
                        out[(size_t)co * P + p] = v;
                    }
                }
            }
        }
    }
}

// ============================================================
// Attention kernels (SIMT fp32, unchanged from R1)
// ============================================================
__global__ void k_transpose() {
    __shared__ float s[32][33];
    int bx = blockIdx.x, by = blockIdx.y;
    int tx = threadIdx.x, ty = threadIdx.y;
#pragma unroll
    for (int i = 0; i < 32; i += 8)
        s[ty + i][tx] = g_x[(by * 32 + ty + i) * 1024 + bx * 32 + tx];
    __syncthreads();
#pragma unroll
    for (int i = 0; i < 32; i += 8)
        g_t[(bx * 32 + ty + i) * 512 + by * 32 + tx] = s[tx][ty + i];
}

__global__ __launch_bounds__(256)
void k_sgemm(const float* __restrict__ A, const float* __restrict__ B,
             float* __restrict__ Cout, int M, int N, int K,
             const float* __restrict__ bias, float* __restrict__ addT) {
    __shared__ float As[16][68];
    __shared__ float Bs[16][64];
    int m0 = blockIdx.y * 64, n0 = blockIdx.x * 64;
    int tid = threadIdx.x;
    int tx = tid & 15, ty = tid >> 4;
    float acc[4][4] = {};
    for (int kk = 0; kk < K; kk += 16) {
        {
            int m = tid >> 2, k4 = (tid & 3) * 4;
            float4 a = *(const float4*)(A + (size_t)(m0 + m) * K + kk + k4);
            As[k4 + 0][m] = a.x; As[k4 + 1][m] = a.y;
            As[k4 + 2][m] = a.z; As[k4 + 3][m] = a.w;
        }
        {
            int k = tid >> 4, n4 = (tid & 15) * 4;
            *(float4*)&Bs[k][n4] = *(const float4*)(B + (size_t)(kk + k) * N + n0 + n4);
        }
        __syncthreads();
#pragma unroll
        for (int k = 0; k < 16; k++) {
            float a[4];
#pragma unroll
            for (int i = 0; i < 4; i++) a[i] = As[k][ty * 4 + i];
            float4 b4 = *(const float4*)&Bs[k][tx * 4];
            float b[4] = {b4.x, b4.y, b4.z, b4.w};
#pragma unroll
            for (int i = 0; i < 4; i++)
#pragma unroll
                for (int j = 0; j < 4; j++) acc[i][j] += a[i] * b[j];
        }
        __syncthreads();
    }
#pragma unroll
    for (int i = 0; i < 4; i++) {
        int m = m0 + ty * 4 + i;
#pragma unroll
        for (int j = 0; j < 4; j++) {
            int n = n0 + tx * 4 + j;
            float v = acc[i][j];
            if (bias) v += bias[n];
            if (addT) addT[(size_t)n * M + m] += v;
            else Cout[(size_t)m * N + n] = v;
        }
    }
}

__global__ __launch_bounds__(256)
void k_attn_scores() {
    __shared__ float Qs[16][68];
    __shared__ float Ks[16][68];
    int h = blockIdx.z;
    int m0 = blockIdx.y * 64, n0 = blockIdx.x * 64;
    int tid = threadIdx.x;
    int tx = tid & 15, ty = tid >> 4;
    int qoff = h * 64, koff = 512 + h * 64;
    float acc[4][4] = {};
    for (int kk = 0; kk < 64; kk += 16) {
        int r = tid >> 2, k4 = (tid & 3) * 4;
        float4 q = *(const float4*)(g_qkv + (size_t)(m0 + r) * 1536 + qoff + kk + k4);
        Qs[k4 + 0][r] = q.x; Qs[k4 + 1][r] = q.y; Qs[k4 + 2][r] = q.z; Qs[k4 + 3][r] = q.w;
        float4 kv = *(const float4*)(g_qkv + (size_t)(n0 + r) * 1536 + koff + kk + k4);
        Ks[k4 + 0][r] = kv.x; Ks[k4 + 1][r] = kv.y; Ks[k4 + 2][r] = kv.z; Ks[k4 + 3][r] = kv.w;
        __syncthreads();
#pragma unroll
        for (int k = 0; k < 16; k++) {
            float a[4], b[4];
#pragma unroll
            for (int i = 0; i < 4; i++) a[i] = Qs[k][ty * 4 + i];
#pragma unroll
            for (int j = 0; j < 4; j++) b[j] = Ks[k][tx * 4 + j];
#pragma unroll
            for (int i = 0; i < 4; i++)
#pragma unroll
                for (int j = 0; j < 4; j++) acc[i][j] += a[i] * b[j];
        }
        __syncthreads();
    }
    float* S = g_attn + ((size_t)h << 20);
#pragma unroll
    for (int i = 0; i < 4; i++)
#pragma unroll
        for (int j = 0; j < 4; j++)
            S[(size_t)(m0 + ty * 4 + i) * 1024 + n0 + tx * 4 + j] = acc[i][j];
}

__global__ __launch_bounds__(256)
void k_softmax(float scale) {
    float* p = g_attn + (size_t)blockIdx.x * 1024;
    int tid = threadIdx.x;
    float4 v = *(float4*)(p + tid * 4);
    v.x *= scale; v.y *= scale; v.z *= scale; v.w *= scale;
    float mx = fmaxf(fmaxf(v.x, v.y), fmaxf(v.z, v.w));
#pragma unroll
    for (int o = 16; o > 0; o >>= 1) mx = fmaxf(mx, __shfl_xor_sync(0xffffffffu, mx, o));
    __shared__ float sm[8], ss[8];
    if ((tid & 31) == 0) sm[tid >> 5] = mx;
    __syncthreads();
    mx = sm[0];
#pragma unroll
    for (int i = 1; i < 8; i++) mx = fmaxf(mx, sm[i]);
    float e0 = expf(v.x - mx), e1 = expf(v.y - mx), e2 = expf(v.z - mx), e3 = expf(v.w - mx);
    float s = e0 + e1 + e2 + e3;
#pragma unroll
    for (int o = 16; o > 0; o >>= 1) s += __shfl_xor_sync(0xffffffffu, s, o);
    if ((tid & 31) == 0) ss[tid >> 5] = s;
    __syncthreads();
    s = ss[0] + ss[1] + ss[2] + ss[3] + ss[4] + ss[5] + ss[6] + ss[7];
    float inv = 1.f / s;
    float4 o4 = make_float4(e0 * inv, e1 * inv, e2 * inv, e3 * inv);
    *(float4*)(p + tid * 4) = o4;
}

__global__ __launch_bounds__(256)
void k_attn_out() {
    __shared__ float As[16][68];
    __shared__ float Bs[16][64];
    int m0 = blockIdx.x * 64, h = blockIdx.y;
    const float* S = g_attn + ((size_t)h << 20);
    int tid = threadIdx.x, tx = tid & 15, ty = tid >> 4;
    float acc[4][4] = {};
    for (int kk = 0; kk < 1024; kk += 16) {
        {
            int m = tid >> 2, k4 = (tid & 3) * 4;
            float4 a = *(const float4*)(S + (size_t)(m0 + m) * 1024 + kk + k4);
            As[k4 + 0][m] = a.x; As[k4 + 1][m] = a.y;
            As[k4 + 2][m] = a.z; As[k4 + 3][m] = a.w;
        }
        {
            int k = tid >> 4, n4 = (tid & 15) * 4;
            *(float4*)&Bs[k][n4] =
                *(const float4*)(g_qkv + (size_t)(kk + k) * 1536 + 1024 + h * 64 + n4);
        }
        __syncthreads();
#pragma unroll
        for (int k = 0; k < 16; k++) {
            float a[4];
#pragma unroll
            for (int i = 0; i < 4; i++) a[i] = As[k][ty * 4 + i];
            float4 b4 = *(const float4*)&Bs[k][tx * 4];
            float b[4] = {b4.x, b4.y, b4.z, b4.w};
#pragma unroll
            for (int i = 0; i < 4; i++)
#pragma unroll
                for (int j = 0; j < 4; j++) acc[i][j] += a[i] * b[j];
        }
        __syncthreads();
    }
#pragma unroll
    for (int i = 0; i < 4; i++)
#pragma unroll
        for (int j = 0; j < 4; j++)
            g_res[(size_t)(m0 + ty * 4 + i) * 512 + h * 64 + tx * 4 + j] = acc[i][j];
}

// ============================================================
// Grid sample, BN fold, c3
// ============================================================
__device__ __forceinline__ int map_idx(int o, int size, bool* valid) {
    float vv = -49.f + 2.f * (float)o;
    float g = (vv + 51.2f) / 102.4f * 2.f - 1.f;
    float f = ((g + 1.f) * (float)size - 1.f) * 0.5f;
    int ii = (int)rintf(f);
    *valid = (ii >= 0) && (ii < size);
    return min(max(ii, 0), size - 1);
}

__global__ void k_gridsample() {
    int idx = blockIdx.x * 256 + threadIdx.x;
    if (idx >= 512 * 2500) return;
    int c = idx / 2500, p = idx - c * 2500;
    int oy = p / 50, ox = p - oy * 50;
    bool vy, vx;
    int iy = map_idx(oy, 32, &vy);
    int ix = map_idx(ox, 32, &vx);
    g_xs[idx] = (vy && vx) ? g_x[(size_t)c * 1024 + iy * 32 + ix] : 0.f;
}

__global__ void k_bnprep(const float* g1, const float* b1, const float* m1, const float* v1,
                         const float* g2, const float* b2, const float* m2, const float* v2) {
    int c = blockIdx.x * 256 + threadIdx.x;
    if (c >= 512) return;
    float s1 = g1[c] / sqrtf(v1[c] + 1e-5f);
    g_bn[c] = s1;
    g_bn[512 + c] = b1[c] - m1[c] * s1;
    float s2 = g2[c] / sqrtf(v2[c] + 1e-5f);
    g_bn[1024 + c] = s2;
    g_bn[1536 + c] = b2[c] - m2[c] * s2;
}

__global__ void k_c3(const float* __restrict__ w, const float* __restrict__ b,
                     float* __restrict__ out) {
    int idx = blockIdx.x * 256 + threadIdx.x;
    if (idx >= 60000) return;
    int cls = idx / 10000, p = idx - cls * 10000;
    const float* wr = w + cls * 512;
    float s = b[cls];
#pragma unroll 4
    for (int c = 0; c < 512; c++) s += g_y1[(size_t)c * 10000 + p] * wr[c];
    out[idx] = 1.f / (1.f + expf(-s));
}

// ============================================================
// Host orchestration
// ============================================================
extern "C" void kernel_launch(void* const* d_in, const int* in_sizes, int n_in,
                              void* d_out, int out_size) {
    const float* x       = (const float*)d_in[0];
    const float* qkv_w   = (const float*)d_in[1];
    const float* proj_w  = (const float*)d_in[2];
    const float* proj_b  = (const float*)d_in[3];
    const float* head_w  = (const float*)d_in[4];
    const float* head_b  = (const float*)d_in[5];
    const float* body_w  = (const float*)d_in[6];
    const float* body_b  = (const float*)d_in[7];
    const float* btail_w = (const float*)d_in[8];
    const float* btail_b = (const float*)d_in[9];
    const float* up_w    = (const float*)d_in[10];
    const float* up_b    = (const float*)d_in[11];
    const float* tail_w  = (const float*)d_in[12];
    const float* tail_b  = (const float*)d_in[13];
    const float* c1_w    = (const float*)d_in[14];
    const float* bn1_g   = (const float*)d_in[15];
    const float* bn1_b   = (const float*)d_in[16];
    const float* bn1_m   = (const float*)d_in[17];
    const float* bn1_v   = (const float*)d_in[18];
    const float* c2_w    = (const float*)d_in[19];
    const float* bn2_g   = (const float*)d_in[20];
    const float* bn2_b   = (const float*)d_in[21];
    const float* bn2_m   = (const float*)d_in[22];
    const float* bn2_v   = (const float*)d_in[23];
    const float* c3_w    = (const float*)d_in[24];
    const float* c3_b    = (const float*)d_in[25];
    float* out = (float*)d_out;

    float *p_x, *p_t, *p_qkv, *p_res, *p_xs, *p_h, *p_r, *p_tmp, *p_u, *p_y1, *p_y2, *p_bn;
    __nv_bfloat16 *p_whi, *p_wlo;
    cudaGetSymbolAddress((void**)&p_x, g_x);
    cudaGetSymbolAddress((void**)&p_t, g_t);
    cudaGetSymbolAddress((void**)&p_qkv, g_qkv);
    cudaGetSymbolAddress((void**)&p_res, g_res);
    cudaGetSymbolAddress((void**)&p_xs, g_xs);
    cudaGetSymbolAddress((void**)&p_h, g_h);
    cudaGetSymbolAddress((void**)&p_r, g_r);
    cudaGetSymbolAddress((void**)&p_tmp, g_tmp);
    cudaGetSymbolAddress((void**)&p_u, g_u);
    cudaGetSymbolAddress((void**)&p_y1, g_y1);
    cudaGetSymbolAddress((void**)&p_y2, g_y2);
    cudaGetSymbolAddress((void**)&p_bn, g_bn);
    cudaGetSymbolAddress((void**)&p_whi, g_whi);
    cudaGetSymbolAddress((void**)&p_wlo, g_wlo);

    cudaFuncSetAttribute(k_convtc, cudaFuncAttributeMaxDynamicSharedMemorySize, SMEM_DYN);

    cudaMemcpyAsync(p_x, x, (size_t)512 * 1024 * sizeof(float),
                    cudaMemcpyDeviceToDevice, 0);

    // ---- weight split prep ----
    {
        struct { const float* s; int off; int n; } regs[7] = {
            {head_w,  W_HEAD,  2359296},
            {body_w,  W_BODY,  37748736},
            {btail_w, W_BTAIL, 2359296},
            {up_w,    W_UP,    9437184},
            {tail_w,  W_TAIL,  2359296},
            {c1_w,    W_C1,    2359296},
            {c2_w,    W_C2,    2359296},
        };
        for (int i = 0; i < 7; i++)
            k_wprep<<<(regs[i].n + 255) / 256, 256>>>(regs[i].s, p_whi + regs[i].off,
                                                      p_wlo + regs[i].off, regs[i].n);
    }

    const float scale = 0.044194173824159216f;  // 512^-0.5

    // ---- 8 self-attention blocks (SIMT) ----
    for (int i = 0; i < 8; i++) {
        k_transpose<<<dim3(32, 16), dim3(32, 8)>>>();
        k_sgemm<<<dim3(24, 16), 256>>>(p_t, qkv_w + (size_t)i * 512 * 1536, p_qkv,
                                       1024, 1536, 512, nullptr, nullptr);
        k_attn_scores<<<dim3(16, 16, 8), 256>>>();
        k_softmax<<<8192, 256>>>(scale);
        k_attn_out<<<dim3(16, 8), 256>>>();
        k_sgemm<<<dim3(8, 16), 256>>>(p_res, proj_w + (size_t)i * 512 * 512, nullptr,
                                      1024, 512, 512, proj_b + (size_t)i * 512, p_x);
    }

    // ---- grid transform + BN fold ----
    k_gridsample<<<(512 * 2500 + 255) / 256, 256>>>();
    k_bnprep<<<2, 256>>>(bn1_g, bn1_b, bn1_m, bn1_v, bn2_g, bn2_b, bn2_m, bn2_v);

    // ---- EDSR upsampler on tensor cores (mma.sync) ----
    dim3 g50(40, 4);     // 2500/64 pixels, 512/128 ch
    k_convtc<<<g50, 256, SMEM_DYN>>>(p_xs, p_whi + W_HEAD, p_wlo + W_HEAD, head_b,
                                     nullptr, nullptr, nullptr, p_h, 50, 50, 0, 0);
    cudaMemcpyAsync(p_r, p_h, (size_t)512 * 2500 * sizeof(float),
                    cudaMemcpyDeviceToDevice, 0);
    for (int i = 0; i < 8; i++) {
        int o0 = W_BODY + (2 * i) * 2359296;
        int o1 = W_BODY + (2 * i + 1) * 2359296;
        k_convtc<<<g50, 256, SMEM_DYN>>>(p_r, p_whi + o0, p_wlo + o0,
                                         body_b + (size_t)(2 * i) * 512,
                                         nullptr, nullptr, nullptr, p_tmp, 50, 50, 1, 0);
        k_convtc<<<g50, 256, SMEM_DYN>>>(p_tmp, p_whi + o1, p_wlo + o1,
                                         body_b + (size_t)(2 * i + 1) * 512,
                                         nullptr, nullptr, p_r, p_r, 50, 50, 0, 0);
    }
    k_convtc<<<g50, 256, SMEM_DYN>>>(p_r, p_whi + W_BTAIL, p_wlo + W_BTAIL, btail_b,
                                     nullptr, nullptr, p_h, p_tmp, 50, 50, 0, 0);
    // up conv 512->2048 with fused pixel shuffle
    k_convtc<<<dim3(40, 16), 256, SMEM_DYN>>>(p_tmp, p_whi + W_UP, p_wlo + W_UP, up_b,
                                              nullptr, nullptr, nullptr, p_u, 50, 50, 0, 1);
    dim3 g100(157, 4);   // 10000/64 pixels
    k_convtc<<<g100, 256, SMEM_DYN>>>(p_u, p_whi + W_TAIL, p_wlo + W_TAIL, tail_b,
                                      nullptr, nullptr, nullptr, p_y1, 100, 100, 0, 0);

    // ---- classifier ----
    k_convtc<<<g100, 256, SMEM_DYN>>>(p_y1, p_whi + W_C1, p_wlo + W_C1, nullptr,
                                      p_bn, p_bn + 512, nullptr, p_y2, 100, 100, 1, 0);
    k_convtc<<<g100, 256, SMEM_DYN>>>(p_y2, p_whi + W_C2, p_wlo + W_C2, nullptr,
                                      p_bn + 1024, p_bn + 1536, nullptr, p_y1, 100, 100, 1, 0);
    k_c3<<<(60000 + 255) / 256, 256>>>(c3_w, c3_b, out);
}